// round 15
// baseline (speedup 1.0000x reference)
#include <cuda_runtime.h>
#include <cuda_fp16.h>
#include <cuda_bf16.h>
#include <cstdint>

// Problem constants: N=25000, K=32, F_IN=F_OUT=256
#define F 256
#define KNEIGH 32
#define N_MAX 25000

// Scratch: z fp16 (12.8 MB), W fp16 bounce (128 KB), monotone barrier counter.
__device__ __half g_z16[(size_t)N_MAX * F];
__device__ __half g_w16[(size_t)F * F];
__device__ unsigned long long g_ctr;   // zero-init; monotone across graph replays

// ---------------------------------------------------------------------------
// Helpers
// ---------------------------------------------------------------------------
__device__ __forceinline__ uint32_t smem_u32(const void* p) {
    return (uint32_t)__cvta_generic_to_shared(p);
}
__device__ __forceinline__ void ldsm_x4(uint32_t* r, uint32_t addr) {
    asm volatile("ldmatrix.sync.aligned.m8n8.x4.shared.b16 {%0,%1,%2,%3}, [%4];"
                 : "=r"(r[0]), "=r"(r[1]), "=r"(r[2]), "=r"(r[3]) : "r"(addr));
}
__device__ __forceinline__ void ldsm_x4_t(uint32_t* r, uint32_t addr) {
    asm volatile("ldmatrix.sync.aligned.m8n8.x4.trans.shared.b16 {%0,%1,%2,%3}, [%4];"
                 : "=r"(r[0]), "=r"(r[1]), "=r"(r[2]), "=r"(r[3]) : "r"(addr));
}
__device__ __forceinline__ void mma_f16(float* d, const uint32_t* a,
                                        uint32_t b0, uint32_t b1) {
    asm volatile(
        "mma.sync.aligned.m16n8k16.row.col.f32.f16.f16.f32 "
        "{%0,%1,%2,%3}, {%4,%5,%6,%7}, {%8,%9}, {%0,%1,%2,%3};"
        : "+f"(d[0]), "+f"(d[1]), "+f"(d[2]), "+f"(d[3])
        : "r"(a[0]), "r"(a[1]), "r"(a[2]), "r"(a[3]), "r"(b0), "r"(b1));
}
__device__ __forceinline__ uint2 pack_half4(float4 v) {
    __half2 h0 = __floats2half2_rn(v.x, v.y);
    __half2 h1 = __floats2half2_rn(v.z, v.w);
    uint2 u;
    u.x = *reinterpret_cast<uint32_t*>(&h0);
    u.y = *reinterpret_cast<uint32_t*>(&h1);
    return u;
}

// ---------------------------------------------------------------------------
// Phase 1: persistent-W GEMM. 148 blocks (1/SM, all co-resident under 202KB
// smem), 256 threads = 8 warps. W startup uses a cooperative fp16 BOUNCE:
// blocks 0..63 convert 1/64th of W fp32->fp16 to g_w16, a monotone-counter
// spin barrier (timeout -> per-block fp32 fallback, bit-identical) publishes
// it, then every block stages 128KB fp16 (18.9MB chip vs 37.9MB fp32).
// Then 64-row x chunks, double-buffered A. Warp tile 32x64 (m16n8k16).
// Mainloop is at the sm_103 register-MMA roofline (~512 MAC/cyc/SM).
// ---------------------------------------------------------------------------
#define CHUNK 64
#define PW 264   // halves per W smem row (pad 8) -> conflict-free ldmatrix
#define PA 264   // halves per A smem row

#define SMEM_W_HALVES (F * PW)                 // 67584 halves = 135168 B
#define SMEM_A_HALVES (CHUNK * PA)             // 16896 halves =  33792 B
#define SMEM_TOTAL_BYTES ((SMEM_W_HALVES + 2 * SMEM_A_HALVES) * 2)  // 202752 B

#define GRID_GEMM 148

__global__ __launch_bounds__(256, 1)
void gemm_relu_persist(const float* __restrict__ A,     // x [M, 256] fp32
                       const float* __restrict__ W,     // W [256, 256] fp32
                       const float* __restrict__ bias,  // [256] fp32
                       int M, int nChunks)
{
    extern __shared__ __align__(16) __half dyn[];
    __half* Ws = dyn;                                   // [256][PW]
    __half* As[2] = { dyn + SMEM_W_HALVES,
                      dyn + SMEM_W_HALVES + SMEM_A_HALVES };
    __shared__ int s_ok;

    const int tid  = threadIdx.x;
    const int lane = tid & 31;
    const int warp = tid >> 5;

    const int warpM = (warp >> 2) * 32;    // {0, 32}
    const int warpN = (warp & 3) * 64;     // {0, 64, 128, 192}
    const int g = lane >> 2;               // 0..7
    const int c = lane & 3;                // 0..3
    const int lmod = lane & 15;
    const int ldiv = lane >> 4;

    int chunk = blockIdx.x;

    // ---- Issue first A-chunk loads (latency hides under W bounce/stage) ----
    float4 va0[16];
    #pragma unroll
    for (int p = 0; p < 16; p++) {
        int i = p * 256 + tid;             // 0..4095 float4s (64 rows x 64 f4)
        int r = i >> 6;
        int c4 = i & 63;
        int row = chunk * CHUNK + r;
        va0[p] = make_float4(0.f, 0.f, 0.f, 0.f);
        if (row < M)
            va0[p] = *reinterpret_cast<const float4*>(&A[(size_t)row * F + c4 * 4]);
    }

    // ---- W bounce: blocks 0..63 convert their 1/64th (256 float4 each) ----
    if (blockIdx.x < 64) {
        int i = blockIdx.x * 256 + tid;    // float4 index 0..16383
        float4 v = reinterpret_cast<const float4*>(W)[i];
        reinterpret_cast<uint2*>(g_w16)[i] = pack_half4(v);
        __threadfence();
    }
    __syncthreads();

    // ---- Monotone-counter barrier (all GRID_GEMM blocks arrive) ----
    if (tid == 0) {
        unsigned long long old = atomicAdd(&g_ctr, 1ULL);
        unsigned long long target = old - (old % (unsigned long long)GRID_GEMM)
                                    + (unsigned long long)GRID_GEMM;
        int it = 0;
        unsigned long long cur;
        do {
            cur = atomicAdd(&g_ctr, 0ULL);
        } while (cur < target && ++it < 200000);
        s_ok = (cur >= target) ? 1 : 0;
    }
    __syncthreads();
    const bool bounce_ok = (s_ok != 0);
    if (bounce_ok) __threadfence();

    // ---- Stage full fp16 W into smem ----
    if (bounce_ok) {
        // 32 uint4 per thread from g_w16 (128 KB), no CVT.
        #pragma unroll 8
        for (int p = 0; p < 32; p++) {
            int i = p * 256 + tid;         // uint4 index 0..8191
            int r = i >> 5;                // row 0..255
            int s = i & 31;                // uint4 within row
            uint4 v = reinterpret_cast<const uint4*>(g_w16)[i];
            *reinterpret_cast<uint4*>(&Ws[r * PW + s * 8]) = v;
        }
    } else {
        // Fallback: direct fp32 read + convert (bit-identical result).
        #pragma unroll 8
        for (int p = 0; p < 64; p++) {
            int i = p * 256 + tid;
            int r = i >> 6;
            int s = i & 63;
            float4 v = reinterpret_cast<const float4*>(W)[i];
            *reinterpret_cast<uint2*>(&Ws[r * PW + s * 4]) = pack_half4(v);
        }
    }

    // ---- Store first A chunk into buffer 0 ----
    #pragma unroll
    for (int p = 0; p < 16; p++) {
        int i = p * 256 + tid;
        int r = i >> 6;
        int c4 = i & 63;
        *reinterpret_cast<uint2*>(&As[0][r * PA + c4 * 4]) = pack_half4(va0[p]);
    }
    __syncthreads();

    int cur = 0;
    while (true) {
        const int next = chunk + gridDim.x;
        const bool hasNext = next < nChunks;

        float acc[2][8][4];
        #pragma unroll
        for (int i = 0; i < 2; i++)
            #pragma unroll
            for (int j = 0; j < 8; j++)
                #pragma unroll
                for (int q = 0; q < 4; q++)
                    acc[i][j][q] = 0.0f;

        float4 va[8];

        #pragma unroll
        for (int h = 0; h < 2; h++) {
            // Prefetch half of next A chunk (rows h*32 .. h*32+31).
            if (hasNext) {
                #pragma unroll
                for (int p = 0; p < 8; p++) {
                    int i = (h * 8 + p) * 256 + tid;
                    int r = i >> 6;
                    int c4 = i & 63;
                    int row = next * CHUNK + r;
                    va[p] = make_float4(0.f, 0.f, 0.f, 0.f);
                    if (row < M)
                        va[p] = *reinterpret_cast<const float4*>(&A[(size_t)row * F + c4 * 4]);
                }
            }
            // Compute k16 steps h*8 .. h*8+7 from buffer cur (W resident).
            #pragma unroll
            for (int ks = 0; ks < 8; ks++) {
                int kk = h * 8 + ks;
                uint32_t aF[2][4];
                #pragma unroll
                for (int tm = 0; tm < 2; tm++) {
                    uint32_t addr = smem_u32(
                        &As[cur][(warpM + tm * 16 + lmod) * PA + kk * 16 + ldiv * 8]);
                    ldsm_x4(aF[tm], addr);
                }
                #pragma unroll
                for (int tn2 = 0; tn2 < 4; tn2++) {
                    uint32_t bF[4];
                    uint32_t addr = smem_u32(
                        &Ws[(kk * 16 + lmod) * PW + warpN + tn2 * 16 + ldiv * 8]);
                    ldsm_x4_t(bF, addr);
                    mma_f16(acc[0][tn2 * 2],     aF[0], bF[0], bF[1]);
                    mma_f16(acc[1][tn2 * 2],     aF[1], bF[0], bF[1]);
                    mma_f16(acc[0][tn2 * 2 + 1], aF[0], bF[2], bF[3]);
                    mma_f16(acc[1][tn2 * 2 + 1], aF[1], bF[2], bF[3]);
                }
            }
            // Store prefetched half into the other buffer.
            if (hasNext) {
                #pragma unroll
                for (int p = 0; p < 8; p++) {
                    int i = (h * 8 + p) * 256 + tid;
                    int r = i >> 6;
                    int c4 = i & 63;
                    *reinterpret_cast<uint2*>(&As[cur ^ 1][r * PA + c4 * 4]) = pack_half4(va[p]);
                }
            }
        }

        // Epilogue: bias + ReLU -> z16 for this chunk.
        #pragma unroll
        for (int tn = 0; tn < 8; tn++) {
            int col = warpN + tn * 8 + c * 2;
            float b0v = bias[col];
            float b1v = bias[col + 1];
            #pragma unroll
            for (int tm = 0; tm < 2; tm++) {
                int row0 = chunk * CHUNK + warpM + tm * 16 + g;
                if (row0 < M) {
                    __half2 hh = __floats2half2_rn(fmaxf(acc[tm][tn][0] + b0v, 0.f),
                                                   fmaxf(acc[tm][tn][1] + b1v, 0.f));
                    *reinterpret_cast<__half2*>(&g_z16[(size_t)row0 * F + col]) = hh;
                }
                int row1 = row0 + 8;
                if (row1 < M) {
                    __half2 hh = __floats2half2_rn(fmaxf(acc[tm][tn][2] + b0v, 0.f),
                                                   fmaxf(acc[tm][tn][3] + b1v, 0.f));
                    *reinterpret_cast<__half2*>(&g_z16[(size_t)row1 * F + col]) = hh;
                }
            }
        }

        if (!hasNext) break;
        __syncthreads();          // next buffer fully written before reading
        chunk = next;
        cur ^= 1;
    }
}

// ---------------------------------------------------------------------------
// Phase 2: out[n] = max_k z16[neigh[n,k]]; one warp per node (R9 = best).
// LDG.64 gathers, batch of 2 neighbors, 6 blocks/SM. Byte offsets shuffled.
// Accumulators init to 0 (ReLU output >= 0, so max >= 0).
// ---------------------------------------------------------------------------
__global__ __launch_bounds__(256, 6)
void pool_max_kernel(const int* __restrict__ neigh,   // [N, 32] int32
                     float* __restrict__ out,         // [N, 256] fp32
                     int N)
{
    const int warp = threadIdx.x >> 5;
    const int lane = threadIdx.x & 31;
    const int n = blockIdx.x * 8 + warp;
    if (n >= N) return;

    int jmine = neigh[(size_t)n * KNEIGH + lane];
    jmine = jmine < 0 ? 0 : (jmine >= N ? N - 1 : jmine);
    int offmine = jmine * (F * 2);                 // byte offset of row

    const char* zbase = reinterpret_cast<const char*>(g_z16);

    __half2 m0 = __float2half2_rn(0.f);
    __half2 m1 = m0, m2 = m0, m3 = m0;

    #pragma unroll
    for (int k = 0; k < KNEIGH; k += 2) {
        uint2 u[2], v[2];
        #pragma unroll
        for (int q = 0; q < 2; q++) {
            int off = __shfl_sync(0xffffffffu, offmine, k + q);
            const uint2* p = reinterpret_cast<const uint2*>(zbase + off);
            u[q] = __ldg(&p[lane]);        // halves [lane*4 .. lane*4+3]
            v[q] = __ldg(&p[32 + lane]);   // halves [128+lane*4 .. +3]
        }
        #pragma unroll
        for (int q = 0; q < 2; q++) {
            m0 = __hmax2(m0, *reinterpret_cast<__half2*>(&u[q].x));
            m1 = __hmax2(m1, *reinterpret_cast<__half2*>(&u[q].y));
            m2 = __hmax2(m2, *reinterpret_cast<__half2*>(&v[q].x));
            m3 = __hmax2(m3, *reinterpret_cast<__half2*>(&v[q].y));
        }
    }

    float4 o0, o1;
    o0.x = __low2float(m0);  o0.y = __high2float(m0);
    o0.z = __low2float(m1);  o0.w = __high2float(m1);
    o1.x = __low2float(m2);  o1.y = __high2float(m2);
    o1.z = __low2float(m3);  o1.w = __high2float(m3);

    *reinterpret_cast<float4*>(&out[(size_t)n * F + lane * 4]) = o0;
    *reinterpret_cast<float4*>(&out[(size_t)n * F + 128 + lane * 4]) = o1;
}

// ---------------------------------------------------------------------------
// Launch: inputs: x (f32), neigh (i32), W (f32), b (f32)
// ---------------------------------------------------------------------------
extern "C" void kernel_launch(void* const* d_in, const int* in_sizes, int n_in,
                              void* d_out, int out_size)
{
    const float* x     = (const float*)d_in[0];
    const int*   neigh = (const int*)d_in[1];
    const float* W     = (const float*)d_in[2];
    const float* bias  = (const float*)d_in[3];
    float*       out   = (float*)d_out;

    const int N = in_sizes[0] / F;                 // 25000
    const int nChunks = (N + CHUNK - 1) / CHUNK;   // 391

    cudaFuncSetAttribute(gemm_relu_persist,
                         cudaFuncAttributeMaxDynamicSharedMemorySize,
                         SMEM_TOTAL_BYTES);

    gemm_relu_persist<<<GRID_GEMM, 256, SMEM_TOTAL_BYTES>>>(x, W, bias, N, nChunks);

    int poolBlocks = (N + 7) / 8;   // 3125
    pool_max_kernel<<<poolBlocks, 256>>>(neigh, out, N);
}

// round 16
// speedup vs baseline: 1.0564x; 1.0564x over previous
#include <cuda_runtime.h>
#include <cuda_fp16.h>
#include <cuda_bf16.h>
#include <cstdint>

// Problem constants: N=25000, K=32, F_IN=F_OUT=256
#define F 256
#define KNEIGH 32
#define N_MAX 25000

// Scratch: z fp16 (12.8 MB).
__device__ __half g_z16[(size_t)N_MAX * F];

// ---------------------------------------------------------------------------
// Helpers
// ---------------------------------------------------------------------------
__device__ __forceinline__ uint32_t smem_u32(const void* p) {
    return (uint32_t)__cvta_generic_to_shared(p);
}
__device__ __forceinline__ void ldsm_x4(uint32_t* r, uint32_t addr) {
    asm volatile("ldmatrix.sync.aligned.m8n8.x4.shared.b16 {%0,%1,%2,%3}, [%4];"
                 : "=r"(r[0]), "=r"(r[1]), "=r"(r[2]), "=r"(r[3]) : "r"(addr));
}
__device__ __forceinline__ void ldsm_x4_t(uint32_t* r, uint32_t addr) {
    asm volatile("ldmatrix.sync.aligned.m8n8.x4.trans.shared.b16 {%0,%1,%2,%3}, [%4];"
                 : "=r"(r[0]), "=r"(r[1]), "=r"(r[2]), "=r"(r[3]) : "r"(addr));
}
__device__ __forceinline__ void mma_f16(float* d, const uint32_t* a,
                                        uint32_t b0, uint32_t b1) {
    asm volatile(
        "mma.sync.aligned.m16n8k16.row.col.f32.f16.f16.f32 "
        "{%0,%1,%2,%3}, {%4,%5,%6,%7}, {%8,%9}, {%0,%1,%2,%3};"
        : "+f"(d[0]), "+f"(d[1]), "+f"(d[2]), "+f"(d[3])
        : "r"(a[0]), "r"(a[1]), "r"(a[2]), "r"(a[3]), "r"(b0), "r"(b1));
}
__device__ __forceinline__ uint2 pack_half4(float4 v) {
    __half2 h0 = __floats2half2_rn(v.x, v.y);
    __half2 h1 = __floats2half2_rn(v.z, v.w);
    uint2 u;
    u.x = *reinterpret_cast<uint32_t*>(&h0);
    u.y = *reinterpret_cast<uint32_t*>(&h1);
    return u;
}

// ---------------------------------------------------------------------------
// Phase 1: persistent-W GEMM (R9/R12 structure = measured best). 152 blocks,
// 256 threads = 8 warps. Full fp16 W (256x256, pitch 264) converted+staged
// once per block (first A-chunk loads issued before W staging for overlap),
// then 64-row x chunks with double-buffered A. Warp tile 32x64 (m16n8k16).
// x is read via __ldcs (read-once streaming) so it does not evict the z
// output from L2 -- z must stay resident for the pool kernel's gathers.
// Mainloop is at the sm_103 register-MMA roofline (~512 MAC/cyc/SM).
// ---------------------------------------------------------------------------
#define CHUNK 64
#define PW 264   // halves per W smem row (pad 8) -> conflict-free ldmatrix
#define PA 264   // halves per A smem row

#define SMEM_W_HALVES (F * PW)                 // 67584 halves = 135168 B
#define SMEM_A_HALVES (CHUNK * PA)             // 16896 halves =  33792 B
#define SMEM_TOTAL_BYTES ((SMEM_W_HALVES + 2 * SMEM_A_HALVES) * 2)  // 202752 B

__global__ __launch_bounds__(256, 1)
void gemm_relu_persist(const float* __restrict__ A,     // x [M, 256] fp32
                       const float* __restrict__ W,     // W [256, 256] fp32
                       const float* __restrict__ bias,  // [256] fp32
                       int M, int nChunks)
{
    extern __shared__ __align__(16) __half dyn[];
    __half* Ws = dyn;                                   // [256][PW]
    __half* As[2] = { dyn + SMEM_W_HALVES,
                      dyn + SMEM_W_HALVES + SMEM_A_HALVES };

    const int tid  = threadIdx.x;
    const int lane = tid & 31;
    const int warp = tid >> 5;

    const int warpM = (warp >> 2) * 32;    // {0, 32}
    const int warpN = (warp & 3) * 64;     // {0, 64, 128, 192}
    const int g = lane >> 2;               // 0..7
    const int c = lane & 3;                // 0..3
    const int lmod = lane & 15;
    const int ldiv = lane >> 4;

    int chunk = blockIdx.x;

    // ---- Issue first A-chunk loads (latency hides under W staging) ----
    float4 va0[16];
    #pragma unroll
    for (int p = 0; p < 16; p++) {
        int i = p * 256 + tid;             // 0..4095 float4s (64 rows x 64 f4)
        int r = i >> 6;
        int c4 = i & 63;
        int row = chunk * CHUNK + r;
        va0[p] = make_float4(0.f, 0.f, 0.f, 0.f);
        if (row < M)
            va0[p] = __ldcs(reinterpret_cast<const float4*>(&A[(size_t)row * F + c4 * 4]));
    }

    // ---- Convert + stage full W fp32 -> fp16 smem (64 float4 per thread) ----
    #pragma unroll 8
    for (int p = 0; p < 64; p++) {
        int i = p * 256 + tid;             // 0..16383 float4
        int r = i >> 6;                    // row 0..255
        int s = i & 63;                    // float4 within row
        float4 v = reinterpret_cast<const float4*>(W)[i];
        *reinterpret_cast<uint2*>(&Ws[r * PW + s * 4]) = pack_half4(v);
    }

    // ---- Store first A chunk into buffer 0 ----
    #pragma unroll
    for (int p = 0; p < 16; p++) {
        int i = p * 256 + tid;
        int r = i >> 6;
        int c4 = i & 63;
        *reinterpret_cast<uint2*>(&As[0][r * PA + c4 * 4]) = pack_half4(va0[p]);
    }
    __syncthreads();

    int cur = 0;
    while (true) {
        const int next = chunk + gridDim.x;
        const bool hasNext = next < nChunks;

        float acc[2][8][4];
        #pragma unroll
        for (int i = 0; i < 2; i++)
            #pragma unroll
            for (int j = 0; j < 8; j++)
                #pragma unroll
                for (int q = 0; q < 4; q++)
                    acc[i][j][q] = 0.0f;

        float4 va[8];

        #pragma unroll
        for (int h = 0; h < 2; h++) {
            // Prefetch half of next A chunk (rows h*32 .. h*32+31).
            if (hasNext) {
                #pragma unroll
                for (int p = 0; p < 8; p++) {
                    int i = (h * 8 + p) * 256 + tid;
                    int r = i >> 6;
                    int c4 = i & 63;
                    int row = next * CHUNK + r;
                    va[p] = make_float4(0.f, 0.f, 0.f, 0.f);
                    if (row < M)
                        va[p] = __ldcs(reinterpret_cast<const float4*>(
                            &A[(size_t)row * F + c4 * 4]));
                }
            }
            // Compute k16 steps h*8 .. h*8+7 from buffer cur (W resident).
            #pragma unroll
            for (int ks = 0; ks < 8; ks++) {
                int kk = h * 8 + ks;
                uint32_t aF[2][4];
                #pragma unroll
                for (int tm = 0; tm < 2; tm++) {
                    uint32_t addr = smem_u32(
                        &As[cur][(warpM + tm * 16 + lmod) * PA + kk * 16 + ldiv * 8]);
                    ldsm_x4(aF[tm], addr);
                }
                #pragma unroll
                for (int tn2 = 0; tn2 < 4; tn2++) {
                    uint32_t bF[4];
                    uint32_t addr = smem_u32(
                        &Ws[(kk * 16 + lmod) * PW + warpN + tn2 * 16 + ldiv * 8]);
                    ldsm_x4_t(bF, addr);
                    mma_f16(acc[0][tn2 * 2],     aF[0], bF[0], bF[1]);
                    mma_f16(acc[1][tn2 * 2],     aF[1], bF[0], bF[1]);
                    mma_f16(acc[0][tn2 * 2 + 1], aF[0], bF[2], bF[3]);
                    mma_f16(acc[1][tn2 * 2 + 1], aF[1], bF[2], bF[3]);
                }
            }
            // Store prefetched half into the other buffer.
            if (hasNext) {
                #pragma unroll
                for (int p = 0; p < 8; p++) {
                    int i = (h * 8 + p) * 256 + tid;
                    int r = i >> 6;
                    int c4 = i & 63;
                    *reinterpret_cast<uint2*>(&As[cur ^ 1][r * PA + c4 * 4]) = pack_half4(va[p]);
                }
            }
        }

        // Epilogue: bias + ReLU -> z16 for this chunk (default policy: z
        // SHOULD stay in L2 for the pool kernel).
        #pragma unroll
        for (int tn = 0; tn < 8; tn++) {
            int col = warpN + tn * 8 + c * 2;
            float b0v = bias[col];
            float b1v = bias[col + 1];
            #pragma unroll
            for (int tm = 0; tm < 2; tm++) {
                int row0 = chunk * CHUNK + warpM + tm * 16 + g;
                if (row0 < M) {
                    __half2 hh = __floats2half2_rn(fmaxf(acc[tm][tn][0] + b0v, 0.f),
                                                   fmaxf(acc[tm][tn][1] + b1v, 0.f));
                    *reinterpret_cast<__half2*>(&g_z16[(size_t)row0 * F + col]) = hh;
                }
                int row1 = row0 + 8;
                if (row1 < M) {
                    __half2 hh = __floats2half2_rn(fmaxf(acc[tm][tn][2] + b0v, 0.f),
                                                   fmaxf(acc[tm][tn][3] + b1v, 0.f));
                    *reinterpret_cast<__half2*>(&g_z16[(size_t)row1 * F + col]) = hh;
                }
            }
        }

        if (!hasNext) break;
        __syncthreads();          // next buffer fully written before reading
        chunk = next;
        cur ^= 1;
    }
}

// ---------------------------------------------------------------------------
// Phase 2: out[n] = max_k z16[neigh[n,k]]; one warp per node (R9 = best).
// LDG.64 gathers, batch of 2 neighbors, 6 blocks/SM. Byte offsets shuffled.
// neigh read via __ldcs (read-once) and out written via __stwt (write-
// through, no L2 allocation) so neither evicts z from L2 mid-gather.
// Accumulators init to 0 (ReLU output >= 0, so max >= 0).
// ---------------------------------------------------------------------------
__global__ __launch_bounds__(256, 6)
void pool_max_kernel(const int* __restrict__ neigh,   // [N, 32] int32
                     float* __restrict__ out,         // [N, 256] fp32
                     int N)
{
    const int warp = threadIdx.x >> 5;
    const int lane = threadIdx.x & 31;
    const int n = blockIdx.x * 8 + warp;
    if (n >= N) return;

    int jmine = __ldcs(&neigh[(size_t)n * KNEIGH + lane]);
    jmine = jmine < 0 ? 0 : (jmine >= N ? N - 1 : jmine);
    int offmine = jmine * (F * 2);                 // byte offset of row

    const char* zbase = reinterpret_cast<const char*>(g_z16);

    __half2 m0 = __float2half2_rn(0.f);
    __half2 m1 = m0, m2 = m0, m3 = m0;

    #pragma unroll
    for (int k = 0; k < KNEIGH; k += 2) {
        uint2 u[2], v[2];
        #pragma unroll
        for (int q = 0; q < 2; q++) {
            int off = __shfl_sync(0xffffffffu, offmine, k + q);
            const uint2* p = reinterpret_cast<const uint2*>(zbase + off);
            u[q] = __ldg(&p[lane]);        // halves [lane*4 .. lane*4+3]
            v[q] = __ldg(&p[32 + lane]);   // halves [128+lane*4 .. +3]
        }
        #pragma unroll
        for (int q = 0; q < 2; q++) {
            m0 = __hmax2(m0, *reinterpret_cast<__half2*>(&u[q].x));
            m1 = __hmax2(m1, *reinterpret_cast<__half2*>(&u[q].y));
            m2 = __hmax2(m2, *reinterpret_cast<__half2*>(&v[q].x));
            m3 = __hmax2(m3, *reinterpret_cast<__half2*>(&v[q].y));
        }
    }

    float4 o0, o1;
    o0.x = __low2float(m0);  o0.y = __high2float(m0);
    o0.z = __low2float(m1);  o0.w = __high2float(m1);
    o1.x = __low2float(m2);  o1.y = __high2float(m2);
    o1.z = __low2float(m3);  o1.w = __high2float(m3);

    __stwt(reinterpret_cast<float4*>(&out[(size_t)n * F + lane * 4]), o0);
    __stwt(reinterpret_cast<float4*>(&out[(size_t)n * F + 128 + lane * 4]), o1);
}

// ---------------------------------------------------------------------------
// Launch: inputs: x (f32), neigh (i32), W (f32), b (f32)
// ---------------------------------------------------------------------------
extern "C" void kernel_launch(void* const* d_in, const int* in_sizes, int n_in,
                              void* d_out, int out_size)
{
    const float* x     = (const float*)d_in[0];
    const int*   neigh = (const int*)d_in[1];
    const float* W     = (const float*)d_in[2];
    const float* bias  = (const float*)d_in[3];
    float*       out   = (float*)d_out;

    const int N = in_sizes[0] / F;                 // 25000
    const int nChunks = (N + CHUNK - 1) / CHUNK;   // 391

    cudaFuncSetAttribute(gemm_relu_persist,
                         cudaFuncAttributeMaxDynamicSharedMemorySize,
                         SMEM_TOTAL_BYTES);

    gemm_relu_persist<<<152, 256, SMEM_TOTAL_BYTES>>>(x, W, bias, N, nChunks);

    int poolBlocks = (N + 7) / 8;   // 3125
    pool_max_kernel<<<poolBlocks, 256>>>(neigh, out, N);
}